// round 6
// baseline (speedup 1.0000x reference)
#include <cuda_runtime.h>
#include <math.h>

#define NB 4096   // tokens
#define DD 1024   // per-tensor dim
#define KD 2048   // concat dim
#define NE 64     // experts
#define TT 32     // tokens per block (dot kernel)
#define KC 32     // K chunk

// Scratch (no cudaMalloc allowed): dot products and expert norms.
__device__ float g_dot[NB * NE];
__device__ float g_gnorm[NE];

// ---------------------------------------------------------------------------
// Kernel 1: ||g_e||^2 per expert. 64 blocks x 256 threads. Trivial cost.
// ---------------------------------------------------------------------------
__global__ __launch_bounds__(256) void gnorm_kernel(const float* __restrict__ gw) {
    int e = blockIdx.x;
    int tid = threadIdx.x;
    float s = 0.f;
    for (int k = tid; k < KD; k += 256) {
        float g = gw[e * KD + k];
        s += g * g;
    }
#pragma unroll
    for (int o = 16; o; o >>= 1) s += __shfl_xor_sync(0xffffffffu, s, o);
    __shared__ float red[8];
    if ((tid & 31) == 0) red[tid >> 5] = s;
    __syncthreads();
    if (tid == 0) {
        float t = 0.f;
#pragma unroll
        for (int i = 0; i < 8; i++) t += red[i];
        g_gnorm[e] = t;
    }
}

// ---------------------------------------------------------------------------
// Kernel 2: dot[t][e] = x_t . g_e   (x = concat(t1, t2))
// Grid 128 blocks (32 tokens each), 128 threads, 4x4 micro-tile per thread.
// Double-buffered smem, k-major (transposed) tiles so compute uses LDS.128.
// FFMA-issue-bound: 16 FMA per 2 LDS.128.
// ---------------------------------------------------------------------------
__global__ __launch_bounds__(128) void dot_kernel(const float* __restrict__ t1,
                                                  const float* __restrict__ t2,
                                                  const float* __restrict__ gw) {
    // pads: 36 and 68 keep float4 alignment for the k-major reads
    __shared__ float xs[2][KC * 36];   // [kk][token]
    __shared__ float gs[2][KC * 68];   // [kk][expert]

    const int tid = threadIdx.x;
    const int tx = tid & 15;   // expert group (4 experts each)
    const int ty = tid >> 4;   // token group  (4 tokens each)
    const int t0 = blockIdx.x * TT;

    float acc[4][4];
#pragma unroll
    for (int i = 0; i < 4; i++)
#pragma unroll
        for (int j = 0; j < 4; j++) acc[i][j] = 0.f;

    float rx[8], rg[16];

    // --- preload chunk 0 (k0 = 0, always in t1) ---
    {
        const float* xsrc = t1 + (size_t)t0 * DD;
#pragma unroll
        for (int i = 0; i < 8; i++) {
            int idx = tid + i * 128;
            int t = idx >> 5, kk = idx & 31;
            rx[i] = xsrc[t * DD + kk];
        }
#pragma unroll
        for (int i = 0; i < 16; i++) {
            int idx = tid + i * 128;
            int e = idx >> 5, kk = idx & 31;
            rg[i] = gw[e * KD + kk];
        }
    }

    const int NCHUNK = KD / KC;  // 64
    for (int c = 0; c < NCHUNK; c++) {
        const int buf = c & 1;
        // stage regs -> smem
#pragma unroll
        for (int i = 0; i < 8; i++) {
            int idx = tid + i * 128;
            int t = idx >> 5, kk = idx & 31;
            xs[buf][kk * 36 + t] = rx[i];
        }
#pragma unroll
        for (int i = 0; i < 16; i++) {
            int idx = tid + i * 128;
            int e = idx >> 5, kk = idx & 31;
            gs[buf][kk * 68 + e] = rg[i];
        }
        __syncthreads();

        // issue next chunk's global loads (latency hides under compute)
        if (c + 1 < NCHUNK) {
            int k0 = (c + 1) * KC;
            const float* xsrc = (k0 < DD) ? (t1 + (size_t)t0 * DD + k0)
                                          : (t2 + (size_t)t0 * DD + (k0 - DD));
#pragma unroll
            for (int i = 0; i < 8; i++) {
                int idx = tid + i * 128;
                int t = idx >> 5, kk = idx & 31;
                rx[i] = xsrc[t * DD + kk];
            }
            const float* gsrc = gw + k0;
#pragma unroll
            for (int i = 0; i < 16; i++) {
                int idx = tid + i * 128;
                int e = idx >> 5, kk = idx & 31;
                rg[i] = gsrc[e * KD + kk];
            }
        }

        // compute: 32 * 16 FMA per thread per chunk
#pragma unroll
        for (int kk = 0; kk < KC; kk++) {
            float4 xv = *(const float4*)&xs[buf][kk * 36 + ty * 4];
            float4 gv = *(const float4*)&gs[buf][kk * 68 + tx * 4];
            float xa[4] = {xv.x, xv.y, xv.z, xv.w};
            float ga[4] = {gv.x, gv.y, gv.z, gv.w};
#pragma unroll
            for (int i = 0; i < 4; i++)
#pragma unroll
                for (int j = 0; j < 4; j++) acc[i][j] += xa[i] * ga[j];
        }
        // NOTE: the barrier at the top of the next iteration separates these
        // reads from the next write to the *other* buffer; same-buffer reuse
        // is two barriers away. One sync per iteration is sufficient.
    }

#pragma unroll
    for (int i = 0; i < 4; i++)
#pragma unroll
        for (int j = 0; j < 4; j++)
            g_dot[(size_t)(t0 + ty * 4 + i) * NE + tx * 4 + j] = acc[i][j];
}

// ---------------------------------------------------------------------------
// Kernel 3: per token (one warp): v_e = ||g_e||^2 - 2*dot (same ordering as
// logits, since ||x||^2 is common-mode). Find two smallest v (lower index on
// ties, matching lax.top_k), compute ||x||^2, true logits -sqrt(d2), softmax
// over the pair, write all 64 outputs.
// ---------------------------------------------------------------------------
__global__ __launch_bounds__(256) void topk_kernel(const float* __restrict__ t1,
                                                   const float* __restrict__ t2,
                                                   float* __restrict__ out) {
    const int gwarp = blockIdx.x * 8 + (threadIdx.x >> 5);
    const int lane = threadIdx.x & 31;
    if (gwarp >= NB) return;
    const int t = gwarp;

    const float BIG = 3.0e38f;
    float v0 = g_gnorm[lane]      - 2.f * g_dot[(size_t)t * NE + lane];
    float v1 = g_gnorm[lane + 32] - 2.f * g_dot[(size_t)t * NE + lane + 32];

    // --- argmin #1 (tie -> lower index) ---
    float bv; int bi;
    if (v0 <= v1) { bv = v0; bi = lane; } else { bv = v1; bi = lane + 32; }
#pragma unroll
    for (int o = 16; o; o >>= 1) {
        float ov = __shfl_xor_sync(0xffffffffu, bv, o);
        int   oi = __shfl_xor_sync(0xffffffffu, bi, o);
        if (ov < bv || (ov == bv && oi < bi)) { bv = ov; bi = oi; }
    }
    const int i1 = bi; const float m1 = bv;

    // --- argmin #2, excluding i1 ---
    float c0 = (lane == i1)      ? BIG : v0;
    float c1 = (lane + 32 == i1) ? BIG : v1;
    if (c0 <= c1) { bv = c0; bi = lane; } else { bv = c1; bi = lane + 32; }
#pragma unroll
    for (int o = 16; o; o >>= 1) {
        float ov = __shfl_xor_sync(0xffffffffu, bv, o);
        int   oi = __shfl_xor_sync(0xffffffffu, bi, o);
        if (ov < bv || (ov == bv && oi < bi)) { bv = ov; bi = oi; }
    }
    const int i2 = bi; const float m2 = bv;

    // --- ||x_t||^2 (warp-cooperative, coalesced float4) ---
    float xn = 0.f;
    const float4* p1 = (const float4*)(t1 + (size_t)t * DD);
    const float4* p2 = (const float4*)(t2 + (size_t)t * DD);
#pragma unroll
    for (int i = 0; i < 8; i++) {
        float4 a = p1[i * 32 + lane];
        xn += a.x * a.x + a.y * a.y + a.z * a.z + a.w * a.w;
        float4 b = p2[i * 32 + lane];
        xn += b.x * b.x + b.y * b.y + b.z * b.z + b.w * b.w;
    }
#pragma unroll
    for (int o = 16; o; o >>= 1) xn += __shfl_xor_sync(0xffffffffu, xn, o);

    // true logits and softmax over the top-2 pair
    float l1 = -sqrtf(fmaxf(xn + m1, 0.f));
    float l2 = -sqrtf(fmaxf(xn + m2, 0.f));
    float w1 = 1.f / (1.f + expf(l2 - l1));   // l2 <= l1
    float w2 = 1.f - w1;

    float o0 = (lane == i1)      ? w1 : ((lane == i2)      ? w2 : 0.f);
    float o1 = (lane + 32 == i1) ? w1 : ((lane + 32 == i2) ? w2 : 0.f);
    out[(size_t)t * NE + lane]      = o0;
    out[(size_t)t * NE + lane + 32] = o1;
}

// ---------------------------------------------------------------------------
extern "C" void kernel_launch(void* const* d_in, const int* in_sizes, int n_in,
                              void* d_out, int out_size) {
    const float* t1 = (const float*)d_in[0];
    const float* t2 = (const float*)d_in[1];
    const float* gw = (const float*)d_in[2];
    float* out = (float*)d_out;

    gnorm_kernel<<<NE, 256>>>(gw);
    dot_kernel<<<NB / TT, 128>>>(t1, t2, gw);
    topk_kernel<<<NB / 8, 256>>>(t1, t2, out);
}